// round 16
// baseline (speedup 1.0000x reference)
#include <cuda_runtime.h>
#include <cuda_fp16.h>

#define NMAX_NODES 50048
#define FEAT 128
#define SLOT 128          // fixed per-node segment capacity (max degree guard)

// Device scratch (no dynamic allocation allowed).
// g_cnt is zero-initialized at module load; gather resets it to zero after
// each use, so every kernel_launch invocation sees zeros (determinism).
__device__ __half g_rep_h[NMAX_NODES * FEAT];     // nodes_rep = F @ W (fp16)
__device__ __half g_Wt[FEAT * FEAT];              // W^T in fp16: g_Wt[n][k]
__device__ int    g_cnt[NMAX_NODES];              // per-node edge counters
__device__ int    g_csr_src[NMAX_NODES * SLOT];   // fixed-slot edge lists

__device__ __forceinline__ void stcs4(float* p, float4 v) {
    asm volatile("st.global.cs.v4.f32 [%0], {%1,%2,%3,%4};"
                 :: "l"(p), "f"(v.x), "f"(v.y), "f"(v.z), "f"(v.w) : "memory");
}
__device__ __forceinline__ void stcs2(float* p, float2 v) {
    asm volatile("st.global.cs.v2.f32 [%0], {%1,%2};"
                 :: "l"(p), "f"(v.x), "f"(v.y) : "memory");
}
__device__ __forceinline__ __half2 h2of2(uint2 v, int i) {
    return ((const __half2*)&v)[i];
}

// ---------------------------------------------------------------------------
// K0: W^T -> fp16. 64 blocks x 256 threads, one element per thread.
// ---------------------------------------------------------------------------
__global__ void wt_kernel(const float* __restrict__ W) {
    int i = blockIdx.x * blockDim.x + threadIdx.x;   // 0..16383
    int n = i >> 7;        // out-feature
    int k = i & 127;       // k index (fast -> coalesced writes)
    g_Wt[i] = __float2half_rn(__ldg(W + k * FEAT + n));
}

// ---------------------------------------------------------------------------
// GEMM block body: fp16 mma.m16n8k16, 128x128 CTA tile, 8 warps (4M x 2N),
// full-K staged once in smem (A cvt f32->f16; B copied from g_Wt).
// Unroll limits keep live ranges short so the 3-CTA reg cap holds w/o spills.
// Epilogue: out[:,0:128] = relu(rep) fp32 (streaming) ; g_rep_h = half(rep).
// ---------------------------------------------------------------------------
__device__ __forceinline__ void gemm_block(
    const float* __restrict__ feat, float* __restrict__ out,
    int n_nodes, int row0, __half (*As)[136], __half (*Bs)[136])
{
    const int tid    = threadIdx.x;
    const int wid    = tid >> 5;
    const int lane   = tid & 31;
    const int gr     = lane >> 2;       // 0..7
    const int gc     = lane & 3;        // 0..3
    const int warp_m = wid & 3;         // 4 warps over M (32 rows)
    const int warp_n = wid >> 2;        // 2 warps over N (64 cols)

    // Stage A: 128 rows x 128 k, f32 -> f16. 4096 float4, 16 per thread.
    #pragma unroll 4
    for (int it = 0; it < 16; it++) {
        int i  = tid + it * 256;        // 0..4095
        int r  = i >> 5;                // row (32 float4 per row)
        int c4 = i & 31;                // float4 index along k
        float4 v = make_float4(0.f, 0.f, 0.f, 0.f);
        int grow = row0 + r;
        if (grow < n_nodes)
            v = *(const float4*)(feat + (size_t)grow * 128 + c4 * 4);
        __half2 h0 = __floats2half2_rn(v.x, v.y);
        __half2 h1 = __floats2half2_rn(v.z, v.w);
        *(__half2*)&As[r][c4 * 4 + 0] = h0;
        *(__half2*)&As[r][c4 * 4 + 2] = h1;
    }
    // Stage B: g_Wt (fp16, [n][k]) -> Bs. 2048 uint4, 8 per thread.
    #pragma unroll 4
    for (int it = 0; it < 8; it++) {
        int i  = tid + it * 256;        // 0..2047
        int r  = i >> 4;                // n row (16 uint4 per row)
        int c8 = i & 15;                // uint4 index along k
        uint4 v = *(const uint4*)(g_Wt + r * 128 + c8 * 8);
        *(uint4*)&Bs[r][c8 * 8] = v;
    }
    __syncthreads();

    float acc[2][8][4];
    #pragma unroll
    for (int mt = 0; mt < 2; mt++)
        #pragma unroll
        for (int nt = 0; nt < 8; nt++)
            #pragma unroll
            for (int i = 0; i < 4; i++) acc[mt][nt][i] = 0.f;

    #pragma unroll 2
    for (int k16 = 0; k16 < 128; k16 += 16) {
        unsigned int a[2][4], b[8][2];
        #pragma unroll
        for (int mt = 0; mt < 2; mt++) {
            int mb = warp_m * 32 + mt * 16;
            a[mt][0] = *(const unsigned int*)&As[mb + gr    ][k16 + gc * 2    ];
            a[mt][1] = *(const unsigned int*)&As[mb + gr + 8][k16 + gc * 2    ];
            a[mt][2] = *(const unsigned int*)&As[mb + gr    ][k16 + gc * 2 + 8];
            a[mt][3] = *(const unsigned int*)&As[mb + gr + 8][k16 + gc * 2 + 8];
        }
        #pragma unroll
        for (int nt = 0; nt < 8; nt++) {
            int nb = warp_n * 64 + nt * 8;
            b[nt][0] = *(const unsigned int*)&Bs[nb + gr][k16 + gc * 2    ];
            b[nt][1] = *(const unsigned int*)&Bs[nb + gr][k16 + gc * 2 + 8];
        }
        #pragma unroll
        for (int mt = 0; mt < 2; mt++)
            #pragma unroll
            for (int nt = 0; nt < 8; nt++) {
                asm("mma.sync.aligned.m16n8k16.row.col.f32.f16.f16.f32 "
                    "{%0,%1,%2,%3}, {%4,%5,%6,%7}, {%8,%9}, {%0,%1,%2,%3};"
                    : "+f"(acc[mt][nt][0]), "+f"(acc[mt][nt][1]),
                      "+f"(acc[mt][nt][2]), "+f"(acc[mt][nt][3])
                    : "r"(a[mt][0]), "r"(a[mt][1]),
                      "r"(a[mt][2]), "r"(a[mt][3]),
                      "r"(b[nt][0]), "r"(b[nt][1]));
            }
    }

    #pragma unroll
    for (int mt = 0; mt < 2; mt++) {
        int row_lo = row0 + warp_m * 32 + mt * 16 + gr;
        int row_hi = row_lo + 8;
        #pragma unroll 4
        for (int nt = 0; nt < 8; nt++) {
            int col = warp_n * 64 + nt * 8 + gc * 2;
            float c0 = acc[mt][nt][0], c1 = acc[mt][nt][1];
            float c2 = acc[mt][nt][2], c3 = acc[mt][nt][3];
            if (row_lo < n_nodes) {
                *(__half2*)(g_rep_h + (size_t)row_lo * 128 + col) =
                    __floats2half2_rn(c0, c1);
                stcs2(out + (size_t)row_lo * 256 + col,
                      make_float2(fmaxf(c0, 0.f), fmaxf(c1, 0.f)));
            }
            if (row_hi < n_nodes) {
                *(__half2*)(g_rep_h + (size_t)row_hi * 128 + col) =
                    __floats2half2_rn(c2, c3);
                stcs2(out + (size_t)row_hi * 256 + col,
                      make_float2(fmaxf(c2, 0.f), fmaxf(c3, 0.f)));
            }
        }
    }
}

// ---------------------------------------------------------------------------
// K1: striped fusion — every 5th block runs a GEMM tile, the other 4 place
// edges directly into fixed slots via zero-based counters.
// 3 CTAs/SM target: smem 69.6KB x 3 = 209KB <= 228KB; reg cap 84 via bounds.
// ---------------------------------------------------------------------------
__global__ __launch_bounds__(256, 3) void gemm_place_kernel(
    const float* __restrict__ feat, float* __restrict__ out,
    int n_nodes, int n_gemm_blocks,
    const int* __restrict__ src, const int* __restrict__ dst, int n_edges)
{
    __shared__ __half As[128][136];
    __shared__ __half Bs[128][136];

    int bid = blockIdx.x;
    int grp = bid / 5, r = bid % 5;
    bool is_gemm;
    int work_idx;
    if (bid < n_gemm_blocks * 5) {
        is_gemm = (r == 4);
        work_idx = is_gemm ? grp : grp * 4 + r;
    } else {
        is_gemm = false;
        work_idx = n_gemm_blocks * 4 + (bid - n_gemm_blocks * 5);
    }

    if (is_gemm) {
        gemm_block(feat, out, n_nodes, work_idx * 128, As, Bs);
    } else {
        int t = work_idx * blockDim.x + threadIdx.x;
        int i0 = t * 4;
        if (i0 + 3 < n_edges) {
            int4 d = *(const int4*)(dst + i0);
            int4 s = *(const int4*)(src + i0);
            int o0 = atomicAdd(&g_cnt[d.x], 1);
            int o1 = atomicAdd(&g_cnt[d.y], 1);
            int o2 = atomicAdd(&g_cnt[d.z], 1);
            int o3 = atomicAdd(&g_cnt[d.w], 1);
            if (o0 < SLOT) g_csr_src[(d.x << 7) + o0] = s.x;
            if (o1 < SLOT) g_csr_src[(d.y << 7) + o1] = s.y;
            if (o2 < SLOT) g_csr_src[(d.z << 7) + o2] = s.z;
            if (o3 < SLOT) g_csr_src[(d.w << 7) + o3] = s.w;
        } else {
            for (int i = i0; i < n_edges; i++) {
                int di = dst[i];
                int off = atomicAdd(&g_cnt[di], 1);
                if (off < SLOT) g_csr_src[(di << 7) + off] = src[i];
            }
        }
    }
}

// ---------------------------------------------------------------------------
// K2: gather — R12 config (at its measured floor ~33.4us). One node per
// full warp, 8B/lane (uint2), 8-edge staged bodies (MLP=8), HADD2 tree.
// Fused mean + relu (streaming). Resets g_cnt[node] = 0 at the end.
// ---------------------------------------------------------------------------
__global__ __launch_bounds__(256, 7) void gather_kernel(float* __restrict__ out,
                                                        int n_nodes)
{
    int node = blockIdx.x * 8 + (threadIdx.x >> 5);
    int lane = threadIdx.x & 31;
    if (node >= n_nodes) return;

    int deg = g_cnt[node];
    int m   = min(deg, SLOT);

    float acc[4];
    #pragma unroll
    for (int i = 0; i < 4; i++) acc[i] = 0.f;

    const __half* repb = g_rep_h + lane * 4;
    const int* idx = g_csr_src + (node << 7);

    int e = 0;
    for (; e + 8 <= m; e += 8) {
        int4 sa = __ldg((const int4*)(idx + e));
        int4 sb = __ldg((const int4*)(idx + e + 4));
        uint2 v0 = __ldg((const uint2*)(repb + (size_t)sa.x * 128));
        uint2 v1 = __ldg((const uint2*)(repb + (size_t)sa.y * 128));
        uint2 v2 = __ldg((const uint2*)(repb + (size_t)sa.z * 128));
        uint2 v3 = __ldg((const uint2*)(repb + (size_t)sa.w * 128));
        uint2 v4 = __ldg((const uint2*)(repb + (size_t)sb.x * 128));
        uint2 v5 = __ldg((const uint2*)(repb + (size_t)sb.y * 128));
        uint2 v6 = __ldg((const uint2*)(repb + (size_t)sb.z * 128));
        uint2 v7 = __ldg((const uint2*)(repb + (size_t)sb.w * 128));
        #pragma unroll
        for (int i = 0; i < 2; i++) {
            __half2 t0 = __hadd2(h2of2(v0, i), h2of2(v1, i));
            __half2 t1 = __hadd2(h2of2(v2, i), h2of2(v3, i));
            __half2 t2 = __hadd2(h2of2(v4, i), h2of2(v5, i));
            __half2 t3 = __hadd2(h2of2(v6, i), h2of2(v7, i));
            __half2 u0 = __hadd2(t0, t1);
            __half2 u1 = __hadd2(t2, t3);
            __half2 w  = __hadd2(u0, u1);
            float2 f = __half22float2(w);
            acc[i * 2 + 0] += f.x;
            acc[i * 2 + 1] += f.y;
        }
    }
    for (; e < m; e++) {
        int s = __ldg(idx + e);
        uint2 v = __ldg((const uint2*)(repb + (size_t)s * 128));
        #pragma unroll
        for (int i = 0; i < 2; i++) {
            float2 f = __half22float2(h2of2(v, i));
            acc[i * 2 + 0] += f.x;
            acc[i * 2 + 1] += f.y;
        }
    }

    float inv = 1.0f / fmaxf((float)deg, 1.0f);
    float4 r = make_float4(fmaxf(acc[0] * inv, 0.f), fmaxf(acc[1] * inv, 0.f),
                           fmaxf(acc[2] * inv, 0.f), fmaxf(acc[3] * inv, 0.f));
    stcs4(out + (size_t)node * 256 + 128 + lane * 4, r);

    // leave counters zeroed for the next invocation (deterministic replays)
    if (lane == 0) g_cnt[node] = 0;
}

// ---------------------------------------------------------------------------
extern "C" void kernel_launch(void* const* d_in, const int* in_sizes, int n_in,
                              void* d_out, int out_size) {
    const float* feat = (const float*)d_in[0];
    const float* W    = (const float*)d_in[1];
    const int*   esrc = (const int*)d_in[2];
    const int*   edst = (const int*)d_in[3];
    float* out = (float*)d_out;

    int n_nodes = in_sizes[0] / FEAT;
    int n_edges = in_sizes[2];

    int gemm_blocks = (n_nodes + 127) / 128;
    int edge_blocks = ((n_edges + 3) / 4 + 255) / 256;
    int extra = edge_blocks > gemm_blocks * 4 ? edge_blocks - gemm_blocks * 4 : 0;
    int k1_blocks = gemm_blocks * 5 + extra;

    wt_kernel<<<64, 256>>>(W);
    gemm_place_kernel<<<k1_blocks, 256>>>(feat, out, n_nodes, gemm_blocks,
                                          esrc, edst, n_edges);
    gather_kernel<<<(n_nodes + 7) / 8, 256>>>(out, n_nodes);
}

// round 17
// speedup vs baseline: 1.5042x; 1.5042x over previous
#include <cuda_runtime.h>
#include <cuda_fp16.h>

#define NMAX_NODES 50048
#define FEAT 128
#define SLOT 128          // fixed per-node segment capacity (max degree guard)

// Device scratch (no dynamic allocation allowed).
// g_cnt is zero-initialized at module load; gather resets it to zero after
// each use, so every kernel_launch invocation sees zeros (determinism).
__device__ __half g_rep_h[NMAX_NODES * FEAT];     // nodes_rep = F @ W (fp16)
__device__ int    g_cnt[NMAX_NODES];              // per-node edge counters
__device__ int    g_csr_src[NMAX_NODES * SLOT];   // fixed-slot edge lists

__device__ __forceinline__ void stcs4(float* p, float4 v) {
    asm volatile("st.global.cs.v4.f32 [%0], {%1,%2,%3,%4};"
                 :: "l"(p), "f"(v.x), "f"(v.y), "f"(v.z), "f"(v.w) : "memory");
}
__device__ __forceinline__ void stcs2(float* p, float2 v) {
    asm volatile("st.global.cs.v2.f32 [%0], {%1,%2};"
                 :: "l"(p), "f"(v.x), "f"(v.y) : "memory");
}
__device__ __forceinline__ __half2 h2of2(uint2 v, int i) {
    return ((const __half2*)&v)[i];
}

// ---------------------------------------------------------------------------
// GEMM block body: fp16 mma.m16n8k16, 128x128 CTA tile, 8 warps (4M x 2N),
// full-K staged once in smem. A: cvt f32->f16 from feat. B: transposed
// in-block from fp32 W (replaces the 4.4us serial wt_kernel launch; reads
// are n-fast coalesced L2 hits, done once per block before the single sync).
// Epilogue: out[:,0:128] = relu(rep) fp32 (streaming) ; g_rep_h = half(rep).
// ---------------------------------------------------------------------------
__device__ __forceinline__ void gemm_block(
    const float* __restrict__ feat, const float* __restrict__ W,
    float* __restrict__ out, int n_nodes, int row0,
    __half (*As)[136], __half (*Bs)[136])
{
    const int tid    = threadIdx.x;
    const int wid    = tid >> 5;
    const int lane   = tid & 31;
    const int gr     = lane >> 2;       // 0..7
    const int gc     = lane & 3;        // 0..3
    const int warp_m = wid & 3;         // 4 warps over M (32 rows)
    const int warp_n = wid >> 2;        // 2 warps over N (64 cols)

    // Stage A: 128 rows x 128 k, f32 -> f16. 4096 float4, 16 per thread.
    #pragma unroll
    for (int it = 0; it < 16; it++) {
        int i  = tid + it * 256;        // 0..4095
        int r  = i >> 5;                // row (32 float4 per row)
        int c4 = i & 31;                // float4 index along k
        float4 v = make_float4(0.f, 0.f, 0.f, 0.f);
        int grow = row0 + r;
        if (grow < n_nodes)
            v = *(const float4*)(feat + (size_t)grow * 128 + c4 * 4);
        __half2 h0 = __floats2half2_rn(v.x, v.y);
        __half2 h1 = __floats2half2_rn(v.z, v.w);
        *(__half2*)&As[r][c4 * 4 + 0] = h0;
        *(__half2*)&As[r][c4 * 4 + 2] = h1;
    }
    // Stage B: transpose W [k][n] f32 -> Bs[n][k] f16.
    // Lane-fast index n => coalesced LDG; 8 k-values per thread => STS.128.
    #pragma unroll
    for (int it = 0; it < 8; it++) {
        int i  = tid + it * 256;        // 0..2047
        int n  = i & 127;               // n (fast -> coalesced reads)
        int c8 = i >> 7;                // which 8-k group
        __half hbuf[8];
        #pragma unroll
        for (int j = 0; j < 8; j++)
            hbuf[j] = __float2half_rn(__ldg(W + (c8 * 8 + j) * FEAT + n));
        *(uint4*)&Bs[n][c8 * 8] = *(const uint4*)hbuf;
    }
    __syncthreads();

    float acc[2][8][4];
    #pragma unroll
    for (int mt = 0; mt < 2; mt++)
        #pragma unroll
        for (int nt = 0; nt < 8; nt++)
            #pragma unroll
            for (int i = 0; i < 4; i++) acc[mt][nt][i] = 0.f;

    #pragma unroll
    for (int k16 = 0; k16 < 128; k16 += 16) {
        unsigned int a[2][4], b[8][2];
        #pragma unroll
        for (int mt = 0; mt < 2; mt++) {
            int mb = warp_m * 32 + mt * 16;
            a[mt][0] = *(const unsigned int*)&As[mb + gr    ][k16 + gc * 2    ];
            a[mt][1] = *(const unsigned int*)&As[mb + gr + 8][k16 + gc * 2    ];
            a[mt][2] = *(const unsigned int*)&As[mb + gr    ][k16 + gc * 2 + 8];
            a[mt][3] = *(const unsigned int*)&As[mb + gr + 8][k16 + gc * 2 + 8];
        }
        #pragma unroll
        for (int nt = 0; nt < 8; nt++) {
            int nb = warp_n * 64 + nt * 8;
            b[nt][0] = *(const unsigned int*)&Bs[nb + gr][k16 + gc * 2    ];
            b[nt][1] = *(const unsigned int*)&Bs[nb + gr][k16 + gc * 2 + 8];
        }
        #pragma unroll
        for (int mt = 0; mt < 2; mt++)
            #pragma unroll
            for (int nt = 0; nt < 8; nt++) {
                asm("mma.sync.aligned.m16n8k16.row.col.f32.f16.f16.f32 "
                    "{%0,%1,%2,%3}, {%4,%5,%6,%7}, {%8,%9}, {%0,%1,%2,%3};"
                    : "+f"(acc[mt][nt][0]), "+f"(acc[mt][nt][1]),
                      "+f"(acc[mt][nt][2]), "+f"(acc[mt][nt][3])
                    : "r"(a[mt][0]), "r"(a[mt][1]),
                      "r"(a[mt][2]), "r"(a[mt][3]),
                      "r"(b[nt][0]), "r"(b[nt][1]));
            }
    }

    #pragma unroll
    for (int mt = 0; mt < 2; mt++) {
        int row_lo = row0 + warp_m * 32 + mt * 16 + gr;
        int row_hi = row_lo + 8;
        #pragma unroll
        for (int nt = 0; nt < 8; nt++) {
            int col = warp_n * 64 + nt * 8 + gc * 2;
            float c0 = acc[mt][nt][0], c1 = acc[mt][nt][1];
            float c2 = acc[mt][nt][2], c3 = acc[mt][nt][3];
            if (row_lo < n_nodes) {
                *(__half2*)(g_rep_h + (size_t)row_lo * 128 + col) =
                    __floats2half2_rn(c0, c1);
                stcs2(out + (size_t)row_lo * 256 + col,
                      make_float2(fmaxf(c0, 0.f), fmaxf(c1, 0.f)));
            }
            if (row_hi < n_nodes) {
                *(__half2*)(g_rep_h + (size_t)row_hi * 128 + col) =
                    __floats2half2_rn(c2, c3);
                stcs2(out + (size_t)row_hi * 256 + col,
                      make_float2(fmaxf(c2, 0.f), fmaxf(c3, 0.f)));
            }
        }
    }
}

// ---------------------------------------------------------------------------
// K1: striped fusion — every 5th block runs a GEMM tile, the other 4 place
// edges directly into fixed slots via zero-based counters.
// (No launch_bounds cap: R15/R16 showed reg caps spill the unrolled GEMM.)
// ---------------------------------------------------------------------------
__global__ __launch_bounds__(256) void gemm_place_kernel(
    const float* __restrict__ feat, const float* __restrict__ W,
    float* __restrict__ out, int n_nodes, int n_gemm_blocks,
    const int* __restrict__ src, const int* __restrict__ dst, int n_edges)
{
    __shared__ __half As[128][136];
    __shared__ __half Bs[128][136];

    int bid = blockIdx.x;
    int grp = bid / 5, r = bid % 5;
    bool is_gemm;
    int work_idx;
    if (bid < n_gemm_blocks * 5) {
        is_gemm = (r == 4);
        work_idx = is_gemm ? grp : grp * 4 + r;
    } else {
        is_gemm = false;
        work_idx = n_gemm_blocks * 4 + (bid - n_gemm_blocks * 5);
    }

    if (is_gemm) {
        gemm_block(feat, W, out, n_nodes, work_idx * 128, As, Bs);
    } else {
        int t = work_idx * blockDim.x + threadIdx.x;
        int i0 = t * 4;
        if (i0 + 3 < n_edges) {
            int4 d = *(const int4*)(dst + i0);
            int4 s = *(const int4*)(src + i0);
            int o0 = atomicAdd(&g_cnt[d.x], 1);
            int o1 = atomicAdd(&g_cnt[d.y], 1);
            int o2 = atomicAdd(&g_cnt[d.z], 1);
            int o3 = atomicAdd(&g_cnt[d.w], 1);
            if (o0 < SLOT) g_csr_src[(d.x << 7) + o0] = s.x;
            if (o1 < SLOT) g_csr_src[(d.y << 7) + o1] = s.y;
            if (o2 < SLOT) g_csr_src[(d.z << 7) + o2] = s.z;
            if (o3 < SLOT) g_csr_src[(d.w << 7) + o3] = s.w;
        } else {
            for (int i = i0; i < n_edges; i++) {
                int di = dst[i];
                int off = atomicAdd(&g_cnt[di], 1);
                if (off < SLOT) g_csr_src[(di << 7) + off] = src[i];
            }
        }
    }
}

// ---------------------------------------------------------------------------
// K2: gather — R12 config (at its measured floor ~33.4us). One node per
// full warp, 8B/lane (uint2), 8-edge staged bodies (MLP=8), HADD2 tree.
// Fused mean + relu (streaming). Resets g_cnt[node] = 0 at the end.
// ---------------------------------------------------------------------------
__global__ __launch_bounds__(256, 7) void gather_kernel(float* __restrict__ out,
                                                        int n_nodes)
{
    int node = blockIdx.x * 8 + (threadIdx.x >> 5);
    int lane = threadIdx.x & 31;
    if (node >= n_nodes) return;

    int deg = g_cnt[node];
    int m   = min(deg, SLOT);

    float acc[4];
    #pragma unroll
    for (int i = 0; i < 4; i++) acc[i] = 0.f;

    const __half* repb = g_rep_h + lane * 4;
    const int* idx = g_csr_src + (node << 7);

    int e = 0;
    for (; e + 8 <= m; e += 8) {
        int4 sa = __ldg((const int4*)(idx + e));
        int4 sb = __ldg((const int4*)(idx + e + 4));
        uint2 v0 = __ldg((const uint2*)(repb + (size_t)sa.x * 128));
        uint2 v1 = __ldg((const uint2*)(repb + (size_t)sa.y * 128));
        uint2 v2 = __ldg((const uint2*)(repb + (size_t)sa.z * 128));
        uint2 v3 = __ldg((const uint2*)(repb + (size_t)sa.w * 128));
        uint2 v4 = __ldg((const uint2*)(repb + (size_t)sb.x * 128));
        uint2 v5 = __ldg((const uint2*)(repb + (size_t)sb.y * 128));
        uint2 v6 = __ldg((const uint2*)(repb + (size_t)sb.z * 128));
        uint2 v7 = __ldg((const uint2*)(repb + (size_t)sb.w * 128));
        #pragma unroll
        for (int i = 0; i < 2; i++) {
            __half2 t0 = __hadd2(h2of2(v0, i), h2of2(v1, i));
            __half2 t1 = __hadd2(h2of2(v2, i), h2of2(v3, i));
            __half2 t2 = __hadd2(h2of2(v4, i), h2of2(v5, i));
            __half2 t3 = __hadd2(h2of2(v6, i), h2of2(v7, i));
            __half2 u0 = __hadd2(t0, t1);
            __half2 u1 = __hadd2(t2, t3);
            __half2 w  = __hadd2(u0, u1);
            float2 f = __half22float2(w);
            acc[i * 2 + 0] += f.x;
            acc[i * 2 + 1] += f.y;
        }
    }
    for (; e < m; e++) {
        int s = __ldg(idx + e);
        uint2 v = __ldg((const uint2*)(repb + (size_t)s * 128));
        #pragma unroll
        for (int i = 0; i < 2; i++) {
            float2 f = __half22float2(h2of2(v, i));
            acc[i * 2 + 0] += f.x;
            acc[i * 2 + 1] += f.y;
        }
    }

    float inv = 1.0f / fmaxf((float)deg, 1.0f);
    float4 r = make_float4(fmaxf(acc[0] * inv, 0.f), fmaxf(acc[1] * inv, 0.f),
                           fmaxf(acc[2] * inv, 0.f), fmaxf(acc[3] * inv, 0.f));
    stcs4(out + (size_t)node * 256 + 128 + lane * 4, r);

    // leave counters zeroed for the next invocation (deterministic replays)
    if (lane == 0) g_cnt[node] = 0;
}

// ---------------------------------------------------------------------------
extern "C" void kernel_launch(void* const* d_in, const int* in_sizes, int n_in,
                              void* d_out, int out_size) {
    const float* feat = (const float*)d_in[0];
    const float* W    = (const float*)d_in[1];
    const int*   esrc = (const int*)d_in[2];
    const int*   edst = (const int*)d_in[3];
    float* out = (float*)d_out;

    int n_nodes = in_sizes[0] / FEAT;
    int n_edges = in_sizes[2];

    int gemm_blocks = (n_nodes + 127) / 128;
    int edge_blocks = ((n_edges + 3) / 4 + 255) / 256;
    int extra = edge_blocks > gemm_blocks * 4 ? edge_blocks - gemm_blocks * 4 : 0;
    int k1_blocks = gemm_blocks * 5 + extra;

    gemm_place_kernel<<<k1_blocks, 256>>>(feat, W, out, n_nodes, gemm_blocks,
                                          esrc, edst, n_edges);
    gather_kernel<<<(n_nodes + 7) / 8, 256>>>(out, n_nodes);
}